// round 1
// baseline (speedup 1.0000x reference)
#include <cuda_runtime.h>

#define NCLS 20
#define NSUP 100
#define NQRY 300
#define DDIM 640
#define NTASK 256
#define THREADS 256
#define QB 4
#define NGRP (NQRY / QB)   // 75
#define ROW4 (DDIM / 4)    // 160 float4 per row

__device__ float g_task_loss[NTASK];

__device__ __forceinline__ unsigned long long pk2(float lo, float hi) {
    unsigned long long r;
    asm("mov.b64 %0, {%1, %2};" : "=l"(r) : "f"(lo), "f"(hi));
    return r;
}
__device__ __forceinline__ unsigned long long ffma2(unsigned long long a,
                                                    unsigned long long b,
                                                    unsigned long long c) {
    unsigned long long d;
    asm("fma.rn.f32x2 %0, %1, %2, %3;" : "=l"(d) : "l"(a), "l"(b), "l"(c));
    return d;
}
__device__ __forceinline__ unsigned long long fadd2(unsigned long long a,
                                                    unsigned long long b) {
    unsigned long long d;
    asm("add.rn.f32x2 %0, %1, %2;" : "=l"(d) : "l"(a), "l"(b));
    return d;
}
__device__ __forceinline__ float2 unpk2(unsigned long long v) {
    float lo, hi;
    asm("mov.b64 {%0, %1}, %2;" : "=f"(lo), "=f"(hi) : "l"(v));
    return make_float2(lo, hi);
}

extern __shared__ float smem_raw[];

__global__ __launch_bounds__(THREADS, 1)
void proto_loss_kernel(const float* __restrict__ sup,
                       const float* __restrict__ qry,
                       const int* __restrict__ tsup,
                       const int* __restrict__ tqry) {
    float* proto = smem_raw;                 // [20][640]
    float* psq   = proto + NCLS * DDIM;      // [20]
    float* wsum  = psq + NCLS;               // [8]
    int*   counts = (int*)(wsum + 8);        // [20]
    int*   labels = counts + NCLS;           // [100]

    const int b    = blockIdx.x;
    const int tid  = threadIdx.x;
    const int lane = tid & 31;
    const int wid  = tid >> 5;

    // ---- Phase 1: prototypes ----
    for (int i = tid; i < NCLS * DDIM; i += THREADS) proto[i] = 0.f;
    if (tid < NCLS) counts[tid] = 0;
    if (tid < NSUP) labels[tid] = tsup[b * NSUP + tid];
    __syncthreads();
    if (tid < NSUP) atomicAdd(&counts[labels[tid]], 1);

    const float* supb = sup + (size_t)b * NSUP * DDIM;
    for (int d = tid; d < DDIM; d += THREADS) {
        #pragma unroll 4
        for (int s = 0; s < NSUP; s++) {
            proto[labels[s] * DDIM + d] += supb[s * DDIM + d];
        }
    }
    __syncthreads();

    #pragma unroll
    for (int c = 0; c < NCLS; c++) {
        float inv = 1.f / (float)counts[c];
        for (int d = tid; d < DDIM; d += THREADS) proto[c * DDIM + d] *= inv;
    }
    __syncthreads();

    // ||p||^2 per class: one warp per class (strided)
    for (int c = wid; c < NCLS; c += 8) {
        float v = 0.f;
        for (int d = lane; d < DDIM; d += 32) {
            float p = proto[c * DDIM + d];
            v = fmaf(p, p, v);
        }
        #pragma unroll
        for (int o = 16; o; o >>= 1) v += __shfl_xor_sync(0xffffffffu, v, o);
        if (!lane) psq[c] = v;
    }
    __syncthreads();

    // ---- Phase 2: queries ----
    const float4* q4 = (const float4*)(qry + (size_t)b * NQRY * DDIM);
    const float4* p4 = (const float4*)proto;
    const int* tqb = tqry + b * NQRY;
    float nll = 0.f;

    for (int g = wid; g < NGRP; g += 8) {
        unsigned long long acc01[NCLS], acc23[NCLS];
        #pragma unroll
        for (int c = 0; c < NCLS; c++) { acc01[c] = 0ull; acc23[c] = 0ull; }
        unsigned long long qs01 = 0ull, qs23 = 0ull;
        const int q0 = g * QB;

        #pragma unroll 1
        for (int ch = 0; ch < 5; ch++) {
            const int i4 = ch * 32 + lane;
            float4 v0 = q4[(q0 + 0) * ROW4 + i4];
            float4 v1 = q4[(q0 + 1) * ROW4 + i4];
            float4 v2 = q4[(q0 + 2) * ROW4 + i4];
            float4 v3 = q4[(q0 + 3) * ROW4 + i4];
            unsigned long long a01[4] = { pk2(v0.x, v1.x), pk2(v0.y, v1.y),
                                          pk2(v0.z, v1.z), pk2(v0.w, v1.w) };
            unsigned long long a23[4] = { pk2(v2.x, v3.x), pk2(v2.y, v3.y),
                                          pk2(v2.z, v3.z), pk2(v2.w, v3.w) };
            #pragma unroll
            for (int d = 0; d < 4; d++) {
                qs01 = ffma2(a01[d], a01[d], qs01);
                qs23 = ffma2(a23[d], a23[d], qs23);
            }
            #pragma unroll
            for (int c = 0; c < NCLS; c++) {
                float4 pv = p4[c * ROW4 + i4];
                unsigned long long pp;
                pp = pk2(pv.x, pv.x);
                acc01[c] = ffma2(a01[0], pp, acc01[c]);
                acc23[c] = ffma2(a23[0], pp, acc23[c]);
                pp = pk2(pv.y, pv.y);
                acc01[c] = ffma2(a01[1], pp, acc01[c]);
                acc23[c] = ffma2(a23[1], pp, acc23[c]);
                pp = pk2(pv.z, pv.z);
                acc01[c] = ffma2(a01[2], pp, acc01[c]);
                acc23[c] = ffma2(a23[2], pp, acc23[c]);
                pp = pk2(pv.w, pv.w);
                acc01[c] = ffma2(a01[3], pp, acc01[c]);
                acc23[c] = ffma2(a23[3], pp, acc23[c]);
            }
        }

        // packed warp reductions
        #pragma unroll
        for (int c = 0; c < NCLS; c++) {
            #pragma unroll
            for (int o = 16; o; o >>= 1) {
                acc01[c] = fadd2(acc01[c], __shfl_xor_sync(0xffffffffu, acc01[c], o));
                acc23[c] = fadd2(acc23[c], __shfl_xor_sync(0xffffffffu, acc23[c], o));
            }
        }
        #pragma unroll
        for (int o = 16; o; o >>= 1) {
            qs01 = fadd2(qs01, __shfl_xor_sync(0xffffffffu, qs01, o));
            qs23 = fadd2(qs23, __shfl_xor_sync(0xffffffffu, qs23, o));
        }
        float2 qsA = unpk2(qs01), qsB = unpk2(qs23);
        float qsq[4] = { qsA.x, qsA.y, qsB.x, qsB.y };

        float cr[4][NCLS];
        #pragma unroll
        for (int c = 0; c < NCLS; c++) {
            float2 x = unpk2(acc01[c]); cr[0][c] = x.x; cr[1][c] = x.y;
            float2 y = unpk2(acc23[c]); cr[2][c] = y.x; cr[3][c] = y.y;
        }

        // log-softmax + NLL (computed redundantly per lane; identical values)
        #pragma unroll
        for (int qi = 0; qi < QB; qi++) {
            int tgt = tqb[q0 + qi];
            float sv[NCLS];
            float m = -1e30f;
            #pragma unroll
            for (int c = 0; c < NCLS; c++) {
                sv[c] = fmaf(2.f, cr[qi][c], -(qsq[qi] + psq[c]));  // s = -dist
                m = fmaxf(m, sv[c]);
            }
            float sum = 0.f, st = 0.f;
            #pragma unroll
            for (int c = 0; c < NCLS; c++) {
                sum += __expf(sv[c] - m);
                if (c == tgt) st = sv[c];
            }
            nll += (m + __logf(sum)) - st;
        }
    }

    if (!lane) wsum[wid] = nll;
    __syncthreads();
    if (tid == 0) {
        float t = 0.f;
        #pragma unroll
        for (int w = 0; w < 8; w++) t += wsum[w];
        g_task_loss[b] = t * (1.f / (float)NQRY);
    }
}

__global__ void final_reduce_kernel(float* __restrict__ out) {
    __shared__ float s[NTASK];
    int tid = threadIdx.x;
    s[tid] = g_task_loss[tid];
    __syncthreads();
    #pragma unroll
    for (int off = 128; off; off >>= 1) {
        if (tid < off) s[tid] += s[tid + off];
        __syncthreads();
    }
    if (tid == 0) out[0] = s[0] * (1.f / (float)NTASK);
}

extern "C" void kernel_launch(void* const* d_in, const int* in_sizes, int n_in,
                              void* d_out, int out_size) {
    const float* sup = (const float*)d_in[0];
    const float* qry = (const float*)d_in[1];
    const int*   ts  = (const int*)d_in[2];
    const int*   tq  = (const int*)d_in[3];
    float* out = (float*)d_out;

    const size_t SMEM = (size_t)(NCLS * DDIM + NCLS + 8) * sizeof(float)
                      + (size_t)(NCLS + NSUP) * sizeof(int);
    cudaFuncSetAttribute(proto_loss_kernel,
                         cudaFuncAttributeMaxDynamicSharedMemorySize, (int)SMEM);
    proto_loss_kernel<<<NTASK, THREADS, SMEM>>>(sup, qry, ts, tq);
    final_reduce_kernel<<<1, NTASK>>>(out);
}

// round 2
// speedup vs baseline: 1.2226x; 1.2226x over previous
#include <cuda_runtime.h>

#define NCLS 20
#define NSUP 100
#define NQRY 300
#define DDIM 640
#define NTASK 256
#define THREADS 256
#define ROW16 (DDIM / 4)      // 160 16-byte elements per row
#define NCHUNK (DDIM / 32)    // 20: 8 lanes x 4 floats per chunk
#define NGRP 38               // ceil(300 / 8) query groups (8 queries per warp-group)

__device__ float g_task_loss[NTASK];
__device__ unsigned int g_ticket = 0;

__device__ __forceinline__ unsigned long long ffma2(unsigned long long a,
                                                    unsigned long long b,
                                                    unsigned long long c) {
    unsigned long long d;
    asm("fma.rn.f32x2 %0, %1, %2, %3;" : "=l"(d) : "l"(a), "l"(b), "l"(c));
    return d;
}
__device__ __forceinline__ unsigned long long fadd2(unsigned long long a,
                                                    unsigned long long b) {
    unsigned long long d;
    asm("add.rn.f32x2 %0, %1, %2;" : "=l"(d) : "l"(a), "l"(b));
    return d;
}
__device__ __forceinline__ float2 unpk2(unsigned long long v) {
    float lo, hi;
    asm("mov.b64 {%0, %1}, %2;" : "=f"(lo), "=f"(hi) : "l"(v));
    return make_float2(lo, hi);
}

extern __shared__ float smem_raw[];

__global__ __launch_bounds__(THREADS, 1)
void proto_loss_kernel(const float* __restrict__ sup,
                       const float* __restrict__ qry,
                       const int* __restrict__ tsup,
                       const int* __restrict__ tqry,
                       float* __restrict__ out) {
    float* proto  = smem_raw;                    // [20][640]
    float* psq    = proto + NCLS * DDIM;         // [20]
    float* wsum   = psq + NCLS;                  // [8]
    int*   counts = (int*)(wsum + 8);            // [20]
    int*   labels = counts + NCLS;               // [100]
    int*   tqs    = labels + NSUP;               // [300]
    int*   flag   = tqs + NQRY;                  // [1]

    const int b    = blockIdx.x;
    const int tid  = threadIdx.x;
    const int lane = tid & 31;
    const int wid  = tid >> 5;
    const int sub  = (lane >> 3);   // subgroup 0..3
    const int sl   = lane & 7;      // lane within subgroup

    // ======== Phase 1: prototypes ========
    for (int i = tid; i < NCLS * DDIM; i += THREADS) proto[i] = 0.f;
    if (tid < NCLS) counts[tid] = 0;
    if (tid < NSUP) labels[tid] = tsup[b * NSUP + tid];
    for (int i = tid; i < NQRY; i += THREADS) tqs[i] = tqry[b * NQRY + i];
    __syncthreads();
    if (tid < NSUP) atomicAdd(&counts[labels[tid]], 1);

    const float* supb = sup + (size_t)b * NSUP * DDIM;
    for (int d = tid; d < DDIM; d += THREADS) {
        int cur = labels[0];
        float run = 0.f;
        #pragma unroll 4
        for (int s = 0; s < NSUP; s++) {
            int L = labels[s];
            if (L != cur) { proto[cur * DDIM + d] += run; run = 0.f; cur = L; }
            run += supb[s * DDIM + d];
        }
        proto[cur * DDIM + d] += run;
    }
    __syncthreads();

    #pragma unroll
    for (int c = 0; c < NCLS; c++) {
        float inv = 1.f / (float)counts[c];
        for (int d = tid; d < DDIM; d += THREADS) proto[c * DDIM + d] *= inv;
    }
    __syncthreads();

    for (int c = wid; c < NCLS; c += 8) {
        float v = 0.f;
        for (int d = lane; d < DDIM; d += 32) {
            float p = proto[c * DDIM + d];
            v = fmaf(p, p, v);
        }
        #pragma unroll
        for (int o = 16; o; o >>= 1) v += __shfl_xor_sync(0xffffffffu, v, o);
        if (!lane) psq[c] = v;
    }
    __syncthreads();

    // ======== Phase 2: query distances + log-softmax ========
    const ulonglong2* q2 = (const ulonglong2*)(qry + (size_t)b * NQRY * DDIM);
    const ulonglong2* p2 = (const ulonglong2*)proto;
    float nll = 0.f;

    for (int g = wid; g < NGRP; g += 8) {
        const int qa = g * 8 + sub * 2;
        const int qb = qa + 1;
        const int qac = qa < NQRY ? qa : NQRY - 1;
        const int qbc = qb < NQRY ? qb : NQRY - 1;

        unsigned long long acc[2 * NCLS];
        #pragma unroll
        for (int k = 0; k < 2 * NCLS; k++) acc[k] = 0ull;

        #pragma unroll 2
        for (int ch = 0; ch < NCHUNK; ch++) {
            const int i4 = ch * 8 + sl;
            ulonglong2 va = q2[qac * ROW16 + i4];
            ulonglong2 vb = q2[qbc * ROW16 + i4];
            #pragma unroll
            for (int c = 0; c < NCLS; c++) {
                ulonglong2 pv = p2[c * ROW16 + i4];   // broadcast across subgroups
                acc[c]        = ffma2(va.x, pv.x, acc[c]);
                acc[c]        = ffma2(va.y, pv.y, acc[c]);
                acc[NCLS + c] = ffma2(vb.x, pv.x, acc[NCLS + c]);
                acc[NCLS + c] = ffma2(vb.y, pv.y, acc[NCLS + c]);
            }
        }

        // 3-round butterfly within the 8-lane subgroup
        #pragma unroll
        for (int k = 0; k < 2 * NCLS; k++) {
            #pragma unroll
            for (int o = 4; o; o >>= 1)
                acc[k] = fadd2(acc[k], __shfl_xor_sync(0xffffffffu, acc[k], o));
        }

        // epilogue: 2 queries per subgroup (redundant across 8 lanes)
        #pragma unroll
        for (int qi = 0; qi < 2; qi++) {
            const int q = qa + qi;
            const int tgt = (q < NQRY) ? tqs[q] : 0;
            float sv[NCLS];
            float m = -1e30f, st = 0.f;
            #pragma unroll
            for (int c = 0; c < NCLS; c++) {
                float2 x = unpk2(acc[qi * NCLS + c]);
                float cr = x.x + x.y;
                sv[c] = fmaf(2.f, cr, -psq[c]);   // -dist + const(q) shift
                m = fmaxf(m, sv[c]);
                if (c == tgt) st = sv[c];
            }
            float sum = 0.f;
            #pragma unroll
            for (int c = 0; c < NCLS; c++) sum += __expf(sv[c] - m);
            if (q < NQRY) nll += (m + __logf(sum)) - st;
        }
    }

    // all 8 lanes of a subgroup hold identical nll; full-warp sum / 8 is exact
    #pragma unroll
    for (int o = 16; o; o >>= 1) nll += __shfl_xor_sync(0xffffffffu, nll, o);
    nll *= 0.125f;

    if (!lane) wsum[wid] = nll;
    __syncthreads();
    if (tid == 0) {
        float t = 0.f;
        #pragma unroll
        for (int w = 0; w < 8; w++) t += wsum[w];
        g_task_loss[b] = t * (1.f / (float)NQRY);
        __threadfence();
        unsigned int v = atomicAdd(&g_ticket, 1u);
        *flag = ((v + 1u) % NTASK == 0u) ? 1 : 0;
    }
    __syncthreads();

    // last CTA of this launch performs the deterministic final reduction
    if (*flag) {
        __threadfence();
        float x = __ldcg(&g_task_loss[tid]);
        float* red = proto;   // reuse smem
        red[tid] = x;
        __syncthreads();
        #pragma unroll
        for (int off = 128; off; off >>= 1) {
            if (tid < off) red[tid] += red[tid + off];
            __syncthreads();
        }
        if (tid == 0) out[0] = red[0] * (1.f / (float)NTASK);
    }
}

extern "C" void kernel_launch(void* const* d_in, const int* in_sizes, int n_in,
                              void* d_out, int out_size) {
    const float* sup = (const float*)d_in[0];
    const float* qry = (const float*)d_in[1];
    const int*   ts  = (const int*)d_in[2];
    const int*   tq  = (const int*)d_in[3];
    float* out = (float*)d_out;

    const size_t SMEM = (size_t)(NCLS * DDIM + NCLS + 8) * sizeof(float)
                      + (size_t)(NCLS + NSUP + NQRY + 1) * sizeof(int);
    cudaFuncSetAttribute(proto_loss_kernel,
                         cudaFuncAttributeMaxDynamicSharedMemorySize, (int)SMEM);
    proto_loss_kernel<<<NTASK, THREADS, SMEM>>>(sup, qry, ts, tq, out);
}

// round 5
// speedup vs baseline: 1.3120x; 1.0731x over previous
#include <cuda_runtime.h>

#define NCLS 20
#define NSUP 100
#define NQRY 300
#define DDIM 640
#define NTASK 256
#define THREADS 256
#define ROW16 (DDIM / 4)      // 160 16-byte elements per row
#define NCHUNK (DDIM / 32)    // 20 chunks: 8 lanes x 4 floats
#define NGRP (NQRY / 4)       // 75 groups: 4 queries per warp-group (1 per subgroup)

__device__ float g_task_loss[NTASK];

__device__ __forceinline__ unsigned long long ffma2(unsigned long long a,
                                                    unsigned long long b,
                                                    unsigned long long c) {
    unsigned long long d;
    asm("fma.rn.f32x2 %0, %1, %2, %3;" : "=l"(d) : "l"(a), "l"(b), "l"(c));
    return d;
}
__device__ __forceinline__ unsigned long long fadd2(unsigned long long a,
                                                    unsigned long long b) {
    unsigned long long d;
    asm("add.rn.f32x2 %0, %1, %2;" : "=l"(d) : "l"(a), "l"(b));
    return d;
}
__device__ __forceinline__ float2 unpk2(unsigned long long v) {
    float lo, hi;
    asm("mov.b64 {%0, %1}, %2;" : "=f"(lo), "=f"(hi) : "l"(v));
    return make_float2(lo, hi);
}

extern __shared__ float smem_raw[];

__global__ __launch_bounds__(THREADS, 2)
void proto_loss_kernel(const float* __restrict__ sup,
                       const float* __restrict__ qry,
                       const int* __restrict__ tsup,
                       const int* __restrict__ tqry) {
    float* proto  = smem_raw;                    // [20][640]
    float* psq    = proto + NCLS * DDIM;         // [20]
    float* wsum   = psq + NCLS;                  // [8]
    int*   counts = (int*)(wsum + 8);            // [20]
    int*   labels = counts + NCLS;               // [100]
    int*   tqs    = labels + NSUP;               // [300]

    const int b    = blockIdx.x;
    const int tid  = threadIdx.x;
    const int lane = tid & 31;
    const int wid  = tid >> 5;
    const int sub  = (lane >> 3);   // subgroup 0..3
    const int sl   = lane & 7;      // lane within subgroup

    // ======== Phase 1: prototypes ========
    for (int i = tid; i < NCLS * DDIM; i += THREADS) proto[i] = 0.f;
    if (tid < NCLS) counts[tid] = 0;
    if (tid < NSUP) labels[tid] = tsup[b * NSUP + tid];
    for (int i = tid; i < NQRY; i += THREADS) tqs[i] = tqry[b * NQRY + i];
    __syncthreads();
    if (tid < NSUP) atomicAdd(&counts[labels[tid]], 1);

    const float* supb = sup + (size_t)b * NSUP * DDIM;
    for (int d = tid; d < DDIM; d += THREADS) {
        int cur = labels[0];
        float run = 0.f;
        #pragma unroll 4
        for (int s = 0; s < NSUP; s++) {
            int L = labels[s];
            if (L != cur) { proto[cur * DDIM + d] += run; run = 0.f; cur = L; }
            run += supb[s * DDIM + d];
        }
        proto[cur * DDIM + d] += run;
    }
    __syncthreads();

    #pragma unroll
    for (int c = 0; c < NCLS; c++) {
        float inv = 1.f / (float)counts[c];
        for (int d = tid; d < DDIM; d += THREADS) proto[c * DDIM + d] *= inv;
    }
    __syncthreads();

    for (int c = wid; c < NCLS; c += 8) {
        float v = 0.f;
        for (int d = lane; d < DDIM; d += 32) {
            float p = proto[c * DDIM + d];
            v = fmaf(p, p, v);
        }
        #pragma unroll
        for (int o = 16; o; o >>= 1) v += __shfl_xor_sync(0xffffffffu, v, o);
        if (!lane) psq[c] = v;
    }
    __syncthreads();

    // ======== Phase 2: query distances + log-softmax ========
    const ulonglong2* q2 = (const ulonglong2*)(qry + (size_t)b * NQRY * DDIM);
    const ulonglong2* p2base = (const ulonglong2*)proto;
    float nll = 0.f;

    for (int g = wid; g < NGRP; g += 8) {
        const int q = g * 4 + sub;   // this subgroup's query (always < 300)
        const ulonglong2* qrow = q2 + (size_t)q * ROW16 + sl;
        const ulonglong2* prow = p2base + sl;

        unsigned long long acc[NCLS];
        #pragma unroll
        for (int c = 0; c < NCLS; c++) acc[c] = 0ull;

        #pragma unroll 2
        for (int ch = 0; ch < NCHUNK; ch++) {
            ulonglong2 va = qrow[ch * 8];
            #pragma unroll
            for (int c = 0; c < NCLS; c++) {
                ulonglong2 pv = prow[c * ROW16 + ch * 8];   // broadcast across subgroups
                acc[c] = ffma2(va.x, pv.x, acc[c]);
                acc[c] = ffma2(va.y, pv.y, acc[c]);
            }
        }

        // 3-round butterfly within the 8-lane subgroup
        #pragma unroll
        for (int c = 0; c < NCLS; c++) {
            #pragma unroll
            for (int o = 4; o; o >>= 1)
                acc[c] = fadd2(acc[c], __shfl_xor_sync(0xffffffffu, acc[c], o));
        }

        // epilogue: 1 query per subgroup (redundant across its 8 lanes)
        {
            const int tgt = tqs[q];
            float sv[NCLS];
            float m = -1e30f, st = 0.f;
            #pragma unroll
            for (int c = 0; c < NCLS; c++) {
                float2 x = unpk2(acc[c]);
                float cr = x.x + x.y;
                sv[c] = fmaf(2.f, cr, -psq[c]);   // -dist + const(q) shift
                m = fmaxf(m, sv[c]);
                if (c == tgt) st = sv[c];
            }
            float sum = 0.f;
            #pragma unroll
            for (int c = 0; c < NCLS; c++) sum += __expf(sv[c] - m);
            nll += (m + __logf(sum)) - st;
        }
    }

    // all 8 lanes of a subgroup hold identical nll; full-warp sum / 8 is exact
    #pragma unroll
    for (int o = 16; o; o >>= 1) nll += __shfl_xor_sync(0xffffffffu, nll, o);
    nll *= 0.125f;

    if (!lane) wsum[wid] = nll;
    __syncthreads();
    if (tid == 0) {
        float t = 0.f;
        #pragma unroll
        for (int w = 0; w < 8; w++) t += wsum[w];
        g_task_loss[b] = t * (1.f / (float)NQRY);
    }
}

__global__ void final_reduce_kernel(float* __restrict__ out) {
    __shared__ float s[NTASK];
    int tid = threadIdx.x;
    s[tid] = g_task_loss[tid];
    __syncthreads();
    #pragma unroll
    for (int off = 128; off; off >>= 1) {
        if (tid < off) s[tid] += s[tid + off];
        __syncthreads();
    }
    if (tid == 0) out[0] = s[0] * (1.f / (float)NTASK);
}

extern "C" void kernel_launch(void* const* d_in, const int* in_sizes, int n_in,
                              void* d_out, int out_size) {
    const float* sup = (const float*)d_in[0];
    const float* qry = (const float*)d_in[1];
    const int*   ts  = (const int*)d_in[2];
    const int*   tq  = (const int*)d_in[3];
    float* out = (float*)d_out;

    const size_t SMEM = (size_t)(NCLS * DDIM + NCLS + 8) * sizeof(float)
                      + (size_t)(NCLS + NSUP + NQRY) * sizeof(int);
    cudaFuncSetAttribute(proto_loss_kernel,
                         cudaFuncAttributeMaxDynamicSharedMemorySize, (int)SMEM);
    proto_loss_kernel<<<NTASK, THREADS, SMEM>>>(sup, qry, ts, tq);
    final_reduce_kernel<<<1, NTASK>>>(out);
}